// round 7
// baseline (speedup 1.0000x reference)
#include <cuda_runtime.h>
#include <math.h>

#define BQ      256      // batch (queries)
#define D       512      // embedding dim
#define NTRAIN  50000    // train rows
#define NATTR   8        // attributes
#define CAP     1024     // per-b matched-sim buffer (mean ~130, 33+ sigma margin)
#define KNB     5        // top-k
#define LMAX    64       // per-row matched-query list cap (P(>64) ~ 0)
#define NBLK    296      // 2 blocks/SM x 148 SMs: all co-resident (required for barrier)
#define NTHR    256
#define NWARPS  (NBLK * 8)

// ---------------- device scratch (no allocations; all counters monotonic => replay-safe) ----
__device__ unsigned long long g_epoch;        // one inc per block per execution
__device__ unsigned long long g_bar;          // device-wide barrier counter
__device__ unsigned long long g_done;         // topk completion counter
__device__ int          g_cnt[2][BQ];         // parity-buffered matched counts (zero-init)
__device__ float        g_sims[BQ * CAP];     // matched (dot * inv_row) per query
__device__ float        g_loss[BQ];           // per-query loss contribution

__global__ void __launch_bounds__(NTHR, 2) fused_kernel(const float* __restrict__ z,
                                                        const int* __restrict__ tattr,
                                                        const float* __restrict__ emb,
                                                        const int* __restrict__ attr,
                                                        float* __restrict__ out) {
    __shared__ unsigned       s_ptgt[BQ];
    __shared__ float          s_sv[8][CAP];    // per-warp top-k scratch (32 KB)
    __shared__ unsigned short s_list[8][LMAX];
    __shared__ int            s_par;

    int t = threadIdx.x, w = t >> 5, lane = t & 31;

    // ---- epoch / parity (monotonic, no reset needed across graph replays) ----
    if (t == 0) {
        unsigned long long e = atomicAdd(&g_epoch, 1ULL);
        s_par = (int)((e / NBLK) & 1ULL);
    }
    // pack all 256 targets into smem (one per thread)
    {
        unsigned p = 0;
        const int* a = tattr + t * NATTR;
        #pragma unroll
        for (int i = 0; i < NATTR; i++) p |= ((unsigned)a[i] & 3u) << (2 * i);
        s_ptgt[t] = p;
    }
    __syncthreads();
    int par = s_par;

    // block 0 zeroes the OTHER parity's counters for the next execution
    if (blockIdx.x == 0 && t < BQ) g_cnt[1 ^ par][t] = 0;

    // ---- phase 1: match + sparse dots (one warp per row, grid-strided) ----
    int gw = blockIdx.x * 8 + w;
    for (int n = gw; n < NTRAIN; n += NWARPS) {
        // pack row attrs (lanes 0..7 contribute one 2-bit field each, OR-reduce)
        unsigned p = 0;
        if (lane < NATTR) p = ((unsigned)attr[(size_t)n * NATTR + lane] & 3u) << (2 * lane);
        #pragma unroll
        for (int o = 16; o; o >>= 1) p |= __shfl_xor_sync(0xffffffffu, p, o);

        // test vs all 256 targets: <=1 mismatching field <=> match_score >= 7
        int nm = 0;
        #pragma unroll
        for (int g = 0; g < BQ; g += 32) {
            unsigned x = p ^ s_ptgt[g + lane];
            unsigned y = (x | (x >> 1)) & 0x5555u;
            bool hit = (__popc(y) <= 1);
            unsigned m = __ballot_sync(0xffffffffu, hit);
            if (hit) {
                int pos = nm + __popc(m & ((1u << lane) - 1u));
                if (pos < LMAX) s_list[w][pos] = (unsigned short)(g + lane);
            }
            nm += __popc(m);
        }
        if (nm == 0) continue;                 // ~51% of rows
        if (nm > LMAX) nm = LMAX;

        // load row once, inv-norm
        const float4* row = (const float4*)(emb + (size_t)n * D);
        float4 r0 = row[lane];
        float4 r1 = row[lane + 32];
        float4 r2 = row[lane + 64];
        float4 r3 = row[lane + 96];
        float ss = r0.x*r0.x + r0.y*r0.y + r0.z*r0.z + r0.w*r0.w
                 + r1.x*r1.x + r1.y*r1.y + r1.z*r1.z + r1.w*r1.w
                 + r2.x*r2.x + r2.y*r2.y + r2.z*r2.z + r2.w*r2.w
                 + r3.x*r3.x + r3.y*r3.y + r3.z*r3.z + r3.w*r3.w;
        #pragma unroll
        for (int o = 16; o; o >>= 1) ss += __shfl_xor_sync(0xffffffffu, ss, o);
        float inv = 1.0f / fmaxf(sqrtf(ss), 1e-12f);

        // dot against raw z[b] (L2-hot); inv_z applied in topk (positive scale keeps order)
        for (int j = 0; j < nm; j++) {
            int b = s_list[w][j];
            const float4* zr = (const float4*)(z + (size_t)b * D);
            float4 z0 = zr[lane];
            float4 z1 = zr[lane + 32];
            float4 z2 = zr[lane + 64];
            float4 z3 = zr[lane + 96];
            float d = r0.x*z0.x + r0.y*z0.y + r0.z*z0.z + r0.w*z0.w
                    + r1.x*z1.x + r1.y*z1.y + r1.z*z1.z + r1.w*z1.w
                    + r2.x*z2.x + r2.y*z2.y + r2.z*z2.z + r2.w*z2.w
                    + r3.x*z3.x + r3.y*z3.y + r3.z*z3.z + r3.w*z3.w;
            #pragma unroll
            for (int o = 16; o; o >>= 1) d += __shfl_xor_sync(0xffffffffu, d, o);
            if (lane == 0) {
                int pos = atomicAdd(&g_cnt[par][b], 1);
                if (pos < CAP) g_sims[(size_t)b * CAP + pos] = d * inv;
            }
        }
    }

    // ---- device-wide barrier (monotonic target: replay-safe, no reset) ----
    __syncthreads();
    if (t == 0) {
        __threadfence();
        unsigned long long my = atomicAdd(&g_bar, 1ULL);
        unsigned long long target = (my / NBLK + 1ULL) * NBLK;
        while (*(volatile unsigned long long*)&g_bar < target) { __nanosleep(64); }
    }
    __syncthreads();
    __threadfence();

    // ---- phase 2: top-5 + per-b loss (warps gw < 256), fused deterministic reduce ----
    if (gw >= BQ) return;
    int b = gw;

    // inv-norm of z[b]
    const float4* zr = (const float4*)(z + (size_t)b * D);
    float4 z0 = zr[lane], z1 = zr[lane + 32], z2 = zr[lane + 64], z3 = zr[lane + 96];
    float ssz = z0.x*z0.x + z0.y*z0.y + z0.z*z0.z + z0.w*z0.w
              + z1.x*z1.x + z1.y*z1.y + z1.z*z1.z + z1.w*z1.w
              + z2.x*z2.x + z2.y*z2.y + z2.z*z2.z + z2.w*z2.w
              + z3.x*z3.x + z3.y*z3.y + z3.z*z3.z + z3.w*z3.w;
    #pragma unroll
    for (int o = 16; o; o >>= 1) ssz += __shfl_xor_sync(0xffffffffu, ssz, o);
    float invz = 1.0f / fmaxf(sqrtf(ssz), 1e-12f);

    int cnt = __ldcg(&g_cnt[par][b]);
    if (cnt > CAP) cnt = CAP;
    for (int i = lane; i < cnt; i += 32) s_sv[w][i] = __ldcg(&g_sims[(size_t)b * CAP + i]);
    __syncwarp();

    // 5 argmax passes; masked_sim has 49k+ zeros so each selection clamps at 0
    float sum5 = 0.0f;
    #pragma unroll
    for (int k = 0; k < KNB; k++) {
        float mx = -1e30f; int mi = -1;
        for (int i = lane; i < cnt; i += 32) {
            float v = s_sv[w][i];
            if (v > mx) { mx = v; mi = i; }
        }
        float bmx = mx;
        #pragma unroll
        for (int o = 16; o; o >>= 1) bmx = fmaxf(bmx, __shfl_xor_sync(0xffffffffu, bmx, o));
        sum5 += fmaxf(bmx, 0.0f);
        unsigned has = __ballot_sync(0xffffffffu, (mx == bmx) && (mi >= 0));
        if (has) {
            int owner = (int)__ffs(has) - 1;
            if (lane == owner) s_sv[w][mi] = -1e30f;   // remove exactly one instance
        }
        __syncwarp();
    }

    if (lane == 0) {
        float per = 1.0f - (invz * sum5) / (float)KNB;
        g_loss[b] = (cnt >= KNB) ? per : 0.0f;
        __threadfence();
    }
    __syncwarp();

    // last topk warp (monotonic counter) sums g_loss in fixed order
    int last = 0;
    if (lane == 0) {
        unsigned long long my = atomicAdd(&g_done, 1ULL);
        last = ((my % BQ) == BQ - 1) ? 1 : 0;
    }
    last = __shfl_sync(0xffffffffu, last, 0);
    if (last) {
        __threadfence();
        float s = 0.0f;
        #pragma unroll
        for (int i = 0; i < BQ / 32; i++)              // fixed order: deterministic
            s += __ldcg(&g_loss[lane + i * 32]);
        #pragma unroll
        for (int o = 16; o; o >>= 1) s += __shfl_xor_sync(0xffffffffu, s, o);
        if (lane == 0) out[0] = s / (float)BQ;
    }
}

extern "C" void kernel_launch(void* const* d_in, const int* in_sizes, int n_in,
                              void* d_out, int out_size) {
    const float* z     = (const float*)d_in[0];   // z_flowed         [256,512]   f32
    const int*   tattr = (const int*)d_in[1];     // target_attrs     [256,8]     i32
    const float* emb   = (const float*)d_in[2];   // train_embeddings [50000,512] f32
    const int*   attr  = (const int*)d_in[3];     // train_attributes [50000,8]   i32
    float*       out   = (float*)d_out;

    fused_kernel<<<NBLK, NTHR>>>(z, tattr, emb, attr, out);
}